// round 1
// baseline (speedup 1.0000x reference)
#include <cuda_runtime.h>
#include <math.h>

#define NQ    100000
#define NL    32
#define NN    100032
#define QD    384
#define LD    1024
#define H     128
#define EE    1000000
#define ESEE  750000
#define EPRED 250000
#define BN_EPS 1e-5f

// ---------------- scratch (static device globals; no allocation) ------------
__device__ __align__(16) float g_xini[NN * H];   // projected input features
__device__ __align__(16) float g_agg [NN * H];   // scatter target / t / x2
__device__ __align__(16) float g_x1  [NN * H];   // layer-1 output
__device__ int   g_src[ESEE];
__device__ int   g_dst[ESEE];
__device__ float g_deg[NN];
__device__ float g_sumew[NN];
__device__ float g_colsum[H];
__device__ float g_colsq[H];
__device__ float g_scale[H];
__device__ float g_shift[H];

// ---------------- input projection: x_ini[0:NQ] = q @ Wq + bq ---------------
// BM=64, BN=128 (full), BK=32, 256 threads, each thread computes 4x8 outputs.
__global__ void proj_q_kernel(const float* __restrict__ A,
                              const float* __restrict__ W,
                              const float* __restrict__ bias) {
    __shared__ __align__(16) float As[64 * 32];
    __shared__ __align__(16) float Ws[32 * 128];
    int tid = threadIdx.x;
    int tx = tid & 15;    // column group 0..15 -> cols tx*8..tx*8+7
    int ty = tid >> 4;    // row group 0..15    -> rows ty*4..ty*4+3
    int row0 = blockIdx.x * 64;

    float acc[4][8];
#pragma unroll
    for (int r = 0; r < 4; r++)
#pragma unroll
        for (int c = 0; c < 8; c++) acc[r][c] = 0.f;

    for (int k0 = 0; k0 < QD; k0 += 32) {
        // A tile 64x32 = 512 float4
#pragma unroll
        for (int i = 0; i < 2; i++) {
            int idx = tid + i * 256;
            int r = idx >> 3;
            int c4 = idx & 7;
            int grow = row0 + r;
            float4 v = make_float4(0.f, 0.f, 0.f, 0.f);
            if (grow < NQ) v = *(const float4*)&A[(long)grow * QD + k0 + c4 * 4];
            *(float4*)&As[r * 32 + c4 * 4] = v;
        }
        // W tile 32x128 = 1024 float4
#pragma unroll
        for (int i = 0; i < 4; i++) {
            int idx = tid + i * 256;
            int r = idx >> 5;
            int c4 = idx & 31;
            *(float4*)&Ws[r * 128 + c4 * 4] = *(const float4*)&W[(k0 + r) * H + c4 * 4];
        }
        __syncthreads();
#pragma unroll
        for (int k = 0; k < 32; k++) {
            float a[4], b[8];
#pragma unroll
            for (int r = 0; r < 4; r++) a[r] = As[(ty * 4 + r) * 32 + k];
#pragma unroll
            for (int c = 0; c < 8; c++) b[c] = Ws[k * 128 + tx * 8 + c];
#pragma unroll
            for (int r = 0; r < 4; r++)
#pragma unroll
                for (int c = 0; c < 8; c++) acc[r][c] += a[r] * b[c];
        }
        __syncthreads();
    }
#pragma unroll
    for (int r = 0; r < 4; r++) {
        int grow = row0 + ty * 4 + r;
        if (grow < NQ) {
#pragma unroll
            for (int c = 0; c < 8; c += 4) {
                float4 v;
                v.x = acc[r][c + 0] + bias[tx * 8 + c + 0];
                v.y = acc[r][c + 1] + bias[tx * 8 + c + 1];
                v.z = acc[r][c + 2] + bias[tx * 8 + c + 2];
                v.w = acc[r][c + 3] + bias[tx * 8 + c + 3];
                *(float4*)&g_xini[grow * H + tx * 8 + c] = v;
            }
        }
    }
}

// ---------------- llm projection (tiny: 32 rows, K=1024) --------------------
__global__ void proj_l_kernel(const float* __restrict__ A,
                              const float* __restrict__ W,
                              const float* __restrict__ b) {
    int i = blockIdx.x;   // 0..31
    int j = threadIdx.x;  // 0..127
    float acc = b[j];
    for (int k = 0; k < LD; k++) acc += A[i * LD + k] * W[k * H + j];
    g_xini[(NQ + i) * H + j] = acc;
}

// ---------------- edge prep: compact src/dst, deg, sum(ew) ------------------
__global__ void edge_prep_kernel(const int* __restrict__ ei,
                                 const int* __restrict__ ecs,
                                 const float* __restrict__ ewt,
                                 const float* __restrict__ Wem,
                                 const float* __restrict__ bem) {
    int i = blockIdx.x * blockDim.x + threadIdx.x;
    if (i >= ESEE) return;
    int e = ecs[i];
    int s = ei[e];
    int d = ei[EE + e];
    g_src[i] = s;
    g_dst[i] = d;
    float v = ewt[e] * Wem[0] + bem[0];
    v = v > 0.f ? v : 0.01f * v;
    atomicAdd(&g_deg[d], 1.f);
    atomicAdd(&g_sumew[d], v);
}

// ---------------- scatter-add of 128-float rows ------------------------------
// 512 threads = 4 edges per block, one thread per feature column.
__global__ void scatter_kernel(const float* __restrict__ x) {
    int e = blockIdx.x * 4 + (threadIdx.x >> 7);
    int c = threadIdx.x & 127;
    int s = g_src[e];
    int d = g_dst[e];
    atomicAdd(&g_agg[d * H + c], x[s * H + c]);
}

// ---------------- layer GEMM + epilogue + BN column stats -------------------
// t = agg @ W + deg*(bm+be) + sumew*We + xprev ; written in-place to g_agg.
__global__ void layer_gemm_kernel(const float* __restrict__ W,
                                  const float* __restrict__ bm,
                                  const float* __restrict__ be,
                                  const float* __restrict__ We,
                                  const float* __restrict__ xprev) {
    __shared__ __align__(16) float As[64 * 32];
    __shared__ __align__(16) float Ws[32 * 128];
    __shared__ float ps[16 * 128];
    __shared__ float pq[16 * 128];
    int tid = threadIdx.x;
    int tx = tid & 15;
    int ty = tid >> 4;
    int row0 = blockIdx.x * 64;

    float acc[4][8];
#pragma unroll
    for (int r = 0; r < 4; r++)
#pragma unroll
        for (int c = 0; c < 8; c++) acc[r][c] = 0.f;

    for (int k0 = 0; k0 < H; k0 += 32) {
#pragma unroll
        for (int i = 0; i < 2; i++) {
            int idx = tid + i * 256;
            int r = idx >> 3;
            int c4 = idx & 7;
            *(float4*)&As[r * 32 + c4 * 4] =
                *(const float4*)&g_agg[(row0 + r) * H + k0 + c4 * 4];
        }
#pragma unroll
        for (int i = 0; i < 4; i++) {
            int idx = tid + i * 256;
            int r = idx >> 5;
            int c4 = idx & 31;
            *(float4*)&Ws[r * 128 + c4 * 4] = *(const float4*)&W[(k0 + r) * H + c4 * 4];
        }
        __syncthreads();
#pragma unroll
        for (int k = 0; k < 32; k++) {
            float a[4], b[8];
#pragma unroll
            for (int r = 0; r < 4; r++) a[r] = As[(ty * 4 + r) * 32 + k];
#pragma unroll
            for (int c = 0; c < 8; c++) b[c] = Ws[k * 128 + tx * 8 + c];
#pragma unroll
            for (int r = 0; r < 4; r++)
#pragma unroll
                for (int c = 0; c < 8; c++) acc[r][c] += a[r] * b[c];
        }
        __syncthreads();
    }

    int col0 = tx * 8;
    float cb[8], we[8];
#pragma unroll
    for (int c = 0; c < 8; c++) {
        cb[c] = bm[col0 + c] + be[col0 + c];
        we[c] = We[col0 + c];
    }
    float lsum[8], lsq[8];
#pragma unroll
    for (int c = 0; c < 8; c++) { lsum[c] = 0.f; lsq[c] = 0.f; }

#pragma unroll
    for (int r = 0; r < 4; r++) {
        int grow = row0 + ty * 4 + r;
        float dg = g_deg[grow];
        float sw = g_sumew[grow];
#pragma unroll
        for (int c = 0; c < 8; c++) {
            float t = acc[r][c] + dg * cb[c] + sw * we[c] + xprev[grow * H + col0 + c];
            acc[r][c] = t;
            lsum[c] += t;
            lsq[c] += t * t;
        }
#pragma unroll
        for (int c = 0; c < 8; c += 4) {
            float4 v;
            v.x = acc[r][c + 0]; v.y = acc[r][c + 1];
            v.z = acc[r][c + 2]; v.w = acc[r][c + 3];
            *(float4*)&g_agg[grow * H + col0 + c] = v;
        }
    }
#pragma unroll
    for (int c = 0; c < 8; c++) {
        ps[ty * 128 + col0 + c] = lsum[c];
        pq[ty * 128 + col0 + c] = lsq[c];
    }
    __syncthreads();
    if (tid < 128) {
        float s = 0.f, q = 0.f;
#pragma unroll
        for (int y = 0; y < 16; y++) {
            s += ps[y * 128 + tid];
            q += pq[y * 128 + tid];
        }
        atomicAdd(&g_colsum[tid], s);
        atomicAdd(&g_colsq[tid], q);
    }
}

// ---------------- BN stat finalize -> affine scale/shift --------------------
__global__ void finalize_kernel(const float* __restrict__ g,
                                const float* __restrict__ beta) {
    int j = threadIdx.x;
    float mu = g_colsum[j] * (1.f / (float)NN);
    float var = g_colsq[j] * (1.f / (float)NN) - mu * mu;
    float rstd = rsqrtf(var + BN_EPS);
    float sc = g[j] * rstd;
    g_scale[j] = sc;
    g_shift[j] = beta[j] - mu * sc;
}

// ---------------- BN apply (+ optional leaky relu) ---------------------------
__global__ void apply_kernel(const float* __restrict__ in,
                             float* __restrict__ out, int do_lrelu) {
    int i = blockIdx.x * blockDim.x + threadIdx.x;  // float4 index
    int c = (i * 4) & 127;
    float4 v = *(const float4*)&in[i * 4];
    v.x = v.x * g_scale[c + 0] + g_shift[c + 0];
    v.y = v.y * g_scale[c + 1] + g_shift[c + 1];
    v.z = v.z * g_scale[c + 2] + g_shift[c + 2];
    v.w = v.w * g_scale[c + 3] + g_shift[c + 3];
    if (do_lrelu) {
        v.x = v.x > 0.f ? v.x : 0.01f * v.x;
        v.y = v.y > 0.f ? v.y : 0.01f * v.y;
        v.z = v.z > 0.f ? v.z : 0.01f * v.z;
        v.w = v.w > 0.f ? v.w : 0.01f * v.w;
    }
    *(float4*)&out[i * 4] = v;
}

// ---------------- edge prediction --------------------------------------------
__global__ void predict_kernel(const int* __restrict__ ei,
                               const int* __restrict__ em,
                               const float* __restrict__ x2,
                               float* __restrict__ out) {
    int warp = (blockIdx.x * blockDim.x + threadIdx.x) >> 5;
    int lane = threadIdx.x & 31;
    if (warp >= EPRED) return;
    int e = em[warp];
    int s = ei[e];
    int t = ei[EE + e];
    float4 a = *(const float4*)&g_xini[s * H + lane * 4];
    float4 b = *(const float4*)&x2[t * H + lane * 4];
    float d = a.x * b.x + a.y * b.y + a.z * b.z + a.w * b.w;
#pragma unroll
    for (int o = 16; o; o >>= 1) d += __shfl_xor_sync(0xffffffffu, d, o);
    if (lane == 0) out[warp] = 1.f / (1.f + expf(-d * (1.f / 128.f)));
}

// ---------------- launch -----------------------------------------------------
extern "C" void kernel_launch(void* const* d_in, const int* in_sizes, int n_in,
                              void* d_out, int out_size) {
    const float* qf  = (const float*)d_in[0];
    const float* lf  = (const float*)d_in[1];
    const int*   ei  = (const int*)d_in[2];
    const int*   em  = (const int*)d_in[3];
    const int*   ecs = (const int*)d_in[4];
    const float* ewt = (const float*)d_in[5];
    const float* Wq  = (const float*)d_in[6];
    const float* bq  = (const float*)d_in[7];
    const float* Wl  = (const float*)d_in[8];
    const float* bl  = (const float*)d_in[9];
    const float* Wem = (const float*)d_in[10];
    const float* bem = (const float*)d_in[11];
    const float* W1m = (const float*)d_in[12];
    const float* b1m = (const float*)d_in[13];
    const float* W1e = (const float*)d_in[14];
    const float* b1e = (const float*)d_in[15];
    const float* W2m = (const float*)d_in[16];
    const float* b2m = (const float*)d_in[17];
    const float* W2e = (const float*)d_in[18];
    const float* b2e = (const float*)d_in[19];
    const float* g1    = (const float*)d_in[20];
    const float* beta1 = (const float*)d_in[21];
    const float* g2    = (const float*)d_in[22];
    const float* beta2 = (const float*)d_in[23];
    float* out = (float*)d_out;

    void *p_agg, *p_xini, *p_x1, *p_deg, *p_sumew, *p_colsum, *p_colsq;
    cudaGetSymbolAddress(&p_agg, g_agg);
    cudaGetSymbolAddress(&p_xini, g_xini);
    cudaGetSymbolAddress(&p_x1, g_x1);
    cudaGetSymbolAddress(&p_deg, g_deg);
    cudaGetSymbolAddress(&p_sumew, g_sumew);
    cudaGetSymbolAddress(&p_colsum, g_colsum);
    cudaGetSymbolAddress(&p_colsq, g_colsq);

    // zero per-node accumulators
    cudaMemsetAsync(p_deg, 0, NN * sizeof(float));
    cudaMemsetAsync(p_sumew, 0, NN * sizeof(float));

    // input projections
    proj_q_kernel<<<NN / 64, 256>>>(qf, Wq, bq);
    proj_l_kernel<<<NL, H>>>(lf, Wl, bl);

    // edge preprocessing (deg, sum_ew, compacted src/dst)
    edge_prep_kernel<<<(ESEE + 255) / 256, 256>>>(ei, ecs, ewt, Wem, bem);

    // ---- layer 1 ----
    cudaMemsetAsync(p_agg, 0, (size_t)NN * H * sizeof(float));
    scatter_kernel<<<ESEE / 4, 512>>>((const float*)p_xini);
    cudaMemsetAsync(p_colsum, 0, H * sizeof(float));
    cudaMemsetAsync(p_colsq, 0, H * sizeof(float));
    layer_gemm_kernel<<<NN / 64, 256>>>(W1m, b1m, b1e, W1e, (const float*)p_xini);
    finalize_kernel<<<1, H>>>(g1, beta1);
    apply_kernel<<<(NN * H / 4) / 256, 256>>>((const float*)p_agg, (float*)p_x1, 1);

    // ---- layer 2 ----
    cudaMemsetAsync(p_agg, 0, (size_t)NN * H * sizeof(float));
    scatter_kernel<<<ESEE / 4, 512>>>((const float*)p_x1);
    cudaMemsetAsync(p_colsum, 0, H * sizeof(float));
    cudaMemsetAsync(p_colsq, 0, H * sizeof(float));
    layer_gemm_kernel<<<NN / 64, 256>>>(W2m, b2m, b2e, W2e, (const float*)p_x1);
    finalize_kernel<<<1, H>>>(g2, beta2);
    apply_kernel<<<(NN * H / 4) / 256, 256>>>((const float*)p_agg, (float*)p_agg, 0);

    // ---- edge prediction ----
    predict_kernel<<<EPRED / 8, 256>>>(ei, em, (const float*)p_agg, out);
}